// round 6
// baseline (speedup 1.0000x reference)
#include <cuda_runtime.h>
#include <cstdint>

#define N_PAT 8192
#define N_BITS 4096
#define DEPTH 8
#define COLBYTES (N_PAT * 2)          // one column = 16 KB contiguous
#define NTHR 512

// c'[i][r] = -state[i]*W[r][i] in {+1,-1}, stored s16.
// Halved domain: g = h/2; flip i => g_new = g + c'[i].
__device__ short g_C[(size_t)N_BITS * N_PAT];  // 64 MB scratch
__device__ int   g_g0[N_PAT];

// ---------------------------------------------------------------------------
__global__ void k_buildU(const float* __restrict__ W, const float* __restrict__ state) {
    __shared__ unsigned char sm[32][132];
    int i0 = blockIdx.x * 32;
    int r0 = blockIdx.y * 128;
    int tx = threadIdx.x, ty = threadIdx.y;
    float v = state[i0 + tx];
    #pragma unroll
    for (int j = 0; j < 16; j++) {
        float w = W[(size_t)(r0 + ty + j * 8) * N_BITS + i0 + tx];
        sm[tx][ty + j * 8] = (w == v) ? 1 : 0;
    }
    __syncthreads();
    #pragma unroll
    for (int jj = 0; jj < 4; jj++) {
        int il = ty + jj * 8;
        short4 val;
        val.x = (short)(1 - 2 * (int)sm[il][4 * tx + 0]);
        val.y = (short)(1 - 2 * (int)sm[il][4 * tx + 1]);
        val.z = (short)(1 - 2 * (int)sm[il][4 * tx + 2]);
        val.w = (short)(1 - 2 * (int)sm[il][4 * tx + 3]);
        *reinterpret_cast<short4*>(&g_C[(size_t)(i0 + il) * N_PAT + r0 + 4 * tx]) = val;
    }
}

// ---------------------------------------------------------------------------
__global__ void k_h0t(const float* __restrict__ state, float* __restrict__ out) {
    int t = blockIdx.x * blockDim.x + threadIdx.x;   // 0..4095 (row pair)
    out[t] = state[t];
    const int* col = reinterpret_cast<const int*>(g_C) + t;
    int acc2 = 0;
    #pragma unroll 8
    for (int i = 0; i < N_BITS; i++)
        acc2 = __vadd2(acc2, col[(size_t)i * (N_PAT / 2)]);
    int lo = (int)(short)(acc2 & 0xFFFF);
    int hi = acc2 >> 16;
    g_g0[2 * t]     = -(lo >> 1);
    g_g0[2 * t + 1] = -(hi >> 1);
}

// ---------------------------------------------------------------------------
// PTX helpers
__device__ __forceinline__ uint32_t smem_u32(const void* p) {
    uint32_t a;
    asm("{ .reg .u64 tmp; cvta.to.shared.u64 tmp, %1; cvt.u32.u64 %0, tmp; }" : "=r"(a) : "l"(p));
    return a;
}
#define MBAR_INIT(a, c) \
    asm volatile("mbarrier.init.shared.b64 [%0], %1;" :: "r"(a), "r"(c) : "memory")
#define FENCE_PROXY_ASYNC() \
    asm volatile("fence.proxy.async.shared::cta;" ::: "memory")
#define MBAR_EXPECT(a, b) \
    asm volatile("mbarrier.arrive.expect_tx.shared.b64 _, [%0], %1;" :: "r"(a), "r"(b) : "memory")
#define BULK_G2S(dst, src, bytes, mb) \
    asm volatile("cp.async.bulk.shared::cta.global.mbarrier::complete_tx::bytes [%0], [%1], %2, [%3];" \
                 :: "r"(dst), "l"(src), "r"(bytes), "r"(mb) : "memory")
#define MBAR_WAIT(a, par) do {                                                        \
    asm volatile(                                                                     \
        "{\n\t.reg .pred P;\n\t"                                                      \
        "WL_%=:\n\t"                                                                  \
        "mbarrier.try_wait.parity.acquire.cta.shared::cta.b64 P, [%0], %1, 0x989680;\n\t" \
        "@P bra.uni WD_%=;\n\t"                                                       \
        "bra.uni WL_%=;\n\t"                                                          \
        "WD_%=:\n\t}"                                                                 \
        :: "r"(a), "r"(par) : "memory");                                              \
} while (0)

// ---------------------------------------------------------------------------
// Main: single CTA, 512 threads, 16 rows/thread as 8 s16x2 regs (g) + m=relu(g).
// Column data flows GMEM->SMEM via cp.async.bulk into an 8-slot ring (one
// 16 KB UBLKCP per step, issued by t0 post-barrier); NO LDG in the loop.
// Exact accept rule: D = sum_r c'*(relu(g+c') + relu(g)) > 0.
// ---------------------------------------------------------------------------
__global__ __launch_bounds__(NTHR, 1)
void k_main(const float* __restrict__ state, const int* __restrict__ perm,
            float* __restrict__ out) {
    extern __shared__ char dyn[];
    short*     ring    = reinterpret_cast<short*>(dyn);                         // 8*16KB
    int*       s_perm  = reinterpret_cast<int*>(dyn + DEPTH * COLBYTES);        // 16KB
    float*     s_state = reinterpret_cast<float*>(dyn + DEPTH * COLBYTES + 16384);
    int*       s_wpart = reinterpret_cast<int*>(dyn + DEPTH * COLBYTES + 32768);// 2*32 ints
    uint64_t*  mbar    = reinterpret_cast<uint64_t*>(dyn + DEPTH * COLBYTES + 32768 + 256);

    int t = threadIdx.x;
    for (int k = t; k < N_BITS; k += NTHR) {
        s_perm[k]  = perm[k];
        s_state[k] = state[k];
    }
    if (t < 32) { s_wpart[t] = 0; s_wpart[32 + t] = 0; }

    uint32_t mb0   = smem_u32(mbar);
    uint32_t ring0 = smem_u32(ring);
    if (t == 0) {
        #pragma unroll
        for (int d = 0; d < DEPTH; d++) MBAR_INIT(mb0 + 8u * d, 1);
        FENCE_PROXY_ASYNC();   // order mbarrier.init (generic proxy) vs bulk-copy (async proxy)
    }

    int g2[8], m2[8];
    #pragma unroll
    for (int k = 0; k < 8; k++) {
        int a = g_g0[t * 16 + 2 * k];
        int b = g_g0[t * 16 + 2 * k + 1];
        g2[k] = (a & 0xFFFF) | (b << 16);
        m2[k] = (max(a, 0) & 0xFFFF) | (max(b, 0) << 16);
    }
    __syncthreads();

    if (t == 0) {   // prologue: fill all ring slots with columns perm[0..DEPTH-1]
        #pragma unroll
        for (int d = 0; d < DEPTH; d++) {
            MBAR_EXPECT(mb0 + 8u * d, COLBYTES);
            BULK_G2S(ring0 + (uint32_t)d * COLBYTES,
                     (const void*)(g_C + (size_t)s_perm[d] * N_PAT),
                     COLBYTES, mb0 + 8u * d);
        }
    }
    MBAR_WAIT(mb0, 0);   // slot 0, phase 0

    #pragma unroll 1
    for (int s = 0; s < N_BITS; s++) {
        const short* Cs = ring + (s & (DEPTH - 1)) * N_PAT + t * 16;
        uint4 cA = *reinterpret_cast<const uint4*>(Cs);
        uint4 cB = *reinterpret_cast<const uint4*>(Cs + 8);

        int gn2[8], mn2[8];
        int D1 = 0, D2 = 0;

#define PAIR2(k, w0, w1) {                                   \
        int gnA = __vadd2(g2[k],     (int)(w0));             \
        int gnB = __vadd2(g2[k + 1], (int)(w1));             \
        gn2[k] = gnA; gn2[k + 1] = gnB;                      \
        int mnA = (int)__vmaxs2((unsigned)gnA, 0u);          \
        int mnB = (int)__vmaxs2((unsigned)gnB, 0u);          \
        mn2[k] = mnA; mn2[k + 1] = mnB;                      \
        int c4 = __byte_perm((int)(w0), (int)(w1), 0x6420);  \
        D1 = __dp2a_lo(mnA, c4, D1);                         \
        D1 = __dp2a_hi(mnB, c4, D1);                         \
        D2 = __dp2a_lo(m2[k], c4, D2);                       \
        D2 = __dp2a_hi(m2[k + 1], c4, D2); }

        PAIR2(0, cA.x, cA.y)
        PAIR2(2, cA.z, cA.w)
        PAIR2(4, cB.x, cB.y)
        PAIR2(6, cB.z, cB.w)
#undef PAIR2

        int d  = D1 + D2;
        int wr = __reduce_add_sync(0xffffffffu, d);
        if ((t & 31) == 0) s_wpart[(s & 1) * 32 + (t >> 5)] = wr;

        // hoisted wait for NEXT step's slot: overlaps the redux/STS above
        if (s + 1 < N_BITS)
            MBAR_WAIT(mb0 + 8u * ((s + 1) & (DEPTH - 1)), ((s + 1) >> 3) & 1);

        __syncthreads();
        int total = __reduce_add_sync(0xffffffffu, s_wpart[(s & 1) * 32 + (t & 31)]);

        // refill the slot just consumed (all reads are pre-barrier -> safe)
        if (t == 0 && s + DEPTH < N_BITS) {
            int ipf = s_perm[s + DEPTH];
            uint32_t mb = mb0 + 8u * (s & (DEPTH - 1));
            MBAR_EXPECT(mb, COLBYTES);
            BULK_G2S(ring0 + (uint32_t)(s & (DEPTH - 1)) * COLBYTES,
                     (const void*)(g_C + (size_t)ipf * N_PAT), COLBYTES, mb);
        }

        if (total > 0) {   // energy strictly decreases -> accept flip
            #pragma unroll
            for (int k = 0; k < 8; k++) { g2[k] = gn2[k]; m2[k] = mn2[k]; }
            if (t == 0) { int ip = s_perm[s]; out[ip] = -s_state[ip]; }
        }
    }
}

// ---------------------------------------------------------------------------
extern "C" void kernel_launch(void* const* d_in, const int* in_sizes, int n_in,
                              void* d_out, int out_size) {
    const float* W     = (const float*)d_in[0];
    const float* state = (const float*)d_in[1];
    const int*   perm  = (const int*)d_in[2];
    float*       out   = (float*)d_out;

    static_assert((DEPTH & (DEPTH - 1)) == 0, "DEPTH must be pow2");
    const int smem_bytes = DEPTH * COLBYTES + 16384 + 16384 + 256 + DEPTH * 8;

    cudaFuncSetAttribute(k_main, cudaFuncAttributeMaxDynamicSharedMemorySize, smem_bytes);

    dim3 b1(32, 8), g1(N_BITS / 32, N_PAT / 128);
    k_buildU<<<g1, b1>>>(W, state);
    k_h0t<<<N_BITS / 256, 256>>>(state, out);
    k_main<<<1, NTHR, smem_bytes>>>(state, perm, out);
}

// round 7
// speedup vs baseline: 1.3008x; 1.3008x over previous
#include <cuda_runtime.h>
#include <cstdint>

#define N_PAT 8192
#define N_BITS 4096
#define NTHR 256          // 8 warps; 32 rows per thread

// c'[i][r] = -state[i]*W[r][i] in {+1,-1}, stored s16.
// Halved domain: g = h/2; flip i => g_new = g + c'[i].
__device__ short g_C[(size_t)N_BITS * N_PAT];  // 64 MB scratch
__device__ int   g_g0[N_PAT];

// ---------------------------------------------------------------------------
__global__ void k_buildU(const float* __restrict__ W, const float* __restrict__ state) {
    __shared__ unsigned char sm[32][132];
    int i0 = blockIdx.x * 32;
    int r0 = blockIdx.y * 128;
    int tx = threadIdx.x, ty = threadIdx.y;
    float v = state[i0 + tx];
    #pragma unroll
    for (int j = 0; j < 16; j++) {
        float w = W[(size_t)(r0 + ty + j * 8) * N_BITS + i0 + tx];
        sm[tx][ty + j * 8] = (w == v) ? 1 : 0;
    }
    __syncthreads();
    #pragma unroll
    for (int jj = 0; jj < 4; jj++) {
        int il = ty + jj * 8;
        short4 val;
        val.x = (short)(1 - 2 * (int)sm[il][4 * tx + 0]);
        val.y = (short)(1 - 2 * (int)sm[il][4 * tx + 1]);
        val.z = (short)(1 - 2 * (int)sm[il][4 * tx + 2]);
        val.w = (short)(1 - 2 * (int)sm[il][4 * tx + 3]);
        *reinterpret_cast<short4*>(&g_C[(size_t)(i0 + il) * N_PAT + r0 + 4 * tx]) = val;
    }
}

// ---------------------------------------------------------------------------
__global__ void k_h0t(const float* __restrict__ state, float* __restrict__ out) {
    int t = blockIdx.x * blockDim.x + threadIdx.x;   // 0..4095 (row pair)
    out[t] = state[t];
    const int* col = reinterpret_cast<const int*>(g_C) + t;
    int acc2 = 0;
    #pragma unroll 8
    for (int i = 0; i < N_BITS; i++)
        acc2 = __vadd2(acc2, col[(size_t)i * (N_PAT / 2)]);
    int lo = (int)(short)(acc2 & 0xFFFF);
    int hi = acc2 >> 16;
    g_g0[2 * t]     = -(lo >> 1);
    g_g0[2 * t + 1] = -(hi >> 1);
}

// ---------------------------------------------------------------------------
// Main: single CTA, 256 threads (8 warps), 32 rows/thread as 16 s16x2 regs
// (g) + m = relu(g). TWO bits per barrier: compute exact deltas
//   D_i  = sum c_i * (relu(g+c_i)      + relu(g))
//   D_j0 = sum c_j * (relu(g+c_j)      + relu(g))          [i rejected]
//   D_j1 = sum c_j * (relu(g+c_i+c_j)  + relu(g+c_i))      [i accepted]
// one STS.128/warp, ONE __syncthreads, LDS.128 + 3x REDUX, decide both bits.
// Columns double-buffered in registers via LDG one group ahead.
// ---------------------------------------------------------------------------
__global__ __launch_bounds__(NTHR, 1)
void k_main(const float* __restrict__ state, const int* __restrict__ perm,
            float* __restrict__ out) {
    __shared__ float s_state[N_BITS];
    __shared__ int   s_perm[N_BITS];
    __shared__ int4  s_wpart[2][32];

    int t = threadIdx.x;
    for (int k = t; k < N_BITS; k += NTHR) {
        s_perm[k]  = perm[k];
        s_state[k] = state[k];
    }
    if (t < 64) reinterpret_cast<int4*>(s_wpart)[t] = make_int4(0, 0, 0, 0);

    const short* __restrict__ Cb = g_C + t * 32;   // this thread's 32-row slice

    int g2[16], m2[16];
    #pragma unroll
    for (int k = 0; k < 16; k++) {
        int a = g_g0[t * 32 + 2 * k];
        int b = g_g0[t * 32 + 2 * k + 1];
        g2[k] = (a & 0xFFFF) | (b << 16);
        m2[k] = (max(a, 0) & 0xFFFF) | (max(b, 0) << 16);
    }
    __syncthreads();

    // column buffers: [parity][4 x uint4] for bit-i and bit-j of a group
    uint4 bI[2][4], bJ[2][4];
    {
        const uint4* ci = reinterpret_cast<const uint4*>(Cb + (size_t)s_perm[0] * N_PAT);
        const uint4* cj = reinterpret_cast<const uint4*>(Cb + (size_t)s_perm[1] * N_PAT);
        #pragma unroll
        for (int q = 0; q < 4; q++) { bI[0][q] = __ldg(ci + q); bJ[0][q] = __ldg(cj + q); }
    }

    #pragma unroll 2
    for (int s = 0; s < N_BITS / 2; s++) {
        int p = s & 1;
        // prefetch next group's two columns (clamped)
        {
            int i2 = min(2 * s + 2, N_BITS - 2);
            int j2 = min(2 * s + 3, N_BITS - 1);
            const uint4* ci = reinterpret_cast<const uint4*>(Cb + (size_t)s_perm[i2] * N_PAT);
            const uint4* cj = reinterpret_cast<const uint4*>(Cb + (size_t)s_perm[j2] * N_PAT);
            #pragma unroll
            for (int q = 0; q < 4; q++) { bI[p ^ 1][q] = __ldg(ci + q); bJ[p ^ 1][q] = __ldg(cj + q); }
        }

        int Di1 = 0, Di2 = 0, Dj01 = 0, Dj02 = 0, Dj11 = 0, Dj12 = 0;

#define W2(k, ci0, ci1, cj0, cj1) {                                      \
        int gi0 = __vadd2(g2[k],     (int)(ci0));                        \
        int gi1 = __vadd2(g2[k + 1], (int)(ci1));                        \
        int gj0 = __vadd2(g2[k],     (int)(cj0));                        \
        int gj1 = __vadd2(g2[k + 1], (int)(cj1));                        \
        int gx0 = __vadd2(gi0,       (int)(cj0));                        \
        int gx1 = __vadd2(gi1,       (int)(cj1));                        \
        int mi0 = (int)__vmaxs2((unsigned)gi0, 0u);                      \
        int mi1 = (int)__vmaxs2((unsigned)gi1, 0u);                      \
        int mj0 = (int)__vmaxs2((unsigned)gj0, 0u);                      \
        int mj1 = (int)__vmaxs2((unsigned)gj1, 0u);                      \
        int mx0 = (int)__vmaxs2((unsigned)gx0, 0u);                      \
        int mx1 = (int)__vmaxs2((unsigned)gx1, 0u);                      \
        int c4i = __byte_perm((int)(ci0), (int)(ci1), 0x6420);           \
        int c4j = __byte_perm((int)(cj0), (int)(cj1), 0x6420);           \
        Di1  = __dp2a_lo(mi0,       c4i, Di1);                           \
        Di1  = __dp2a_hi(mi1,       c4i, Di1);                           \
        Di2  = __dp2a_lo(m2[k],     c4i, Di2);                           \
        Di2  = __dp2a_hi(m2[k + 1], c4i, Di2);                           \
        Dj01 = __dp2a_lo(mj0,       c4j, Dj01);                          \
        Dj01 = __dp2a_hi(mj1,       c4j, Dj01);                          \
        Dj02 = __dp2a_lo(m2[k],     c4j, Dj02);                          \
        Dj02 = __dp2a_hi(m2[k + 1], c4j, Dj02);                          \
        Dj11 = __dp2a_lo(mx0,       c4j, Dj11);                          \
        Dj11 = __dp2a_hi(mx1,       c4j, Dj11);                          \
        Dj12 = __dp2a_lo(mi0,       c4j, Dj12);                          \
        Dj12 = __dp2a_hi(mi1,       c4j, Dj12); }

        W2(0,  bI[p][0].x, bI[p][0].y, bJ[p][0].x, bJ[p][0].y)
        W2(2,  bI[p][0].z, bI[p][0].w, bJ[p][0].z, bJ[p][0].w)
        W2(4,  bI[p][1].x, bI[p][1].y, bJ[p][1].x, bJ[p][1].y)
        W2(6,  bI[p][1].z, bI[p][1].w, bJ[p][1].z, bJ[p][1].w)
        W2(8,  bI[p][2].x, bI[p][2].y, bJ[p][2].x, bJ[p][2].y)
        W2(10, bI[p][2].z, bI[p][2].w, bJ[p][2].z, bJ[p][2].w)
        W2(12, bI[p][3].x, bI[p][3].y, bJ[p][3].x, bJ[p][3].y)
        W2(14, bI[p][3].z, bI[p][3].w, bJ[p][3].z, bJ[p][3].w)
#undef W2

        int wDi  = __reduce_add_sync(0xffffffffu, Di1 + Di2);
        int wDj0 = __reduce_add_sync(0xffffffffu, Dj01 + Dj02);
        int wDj1 = __reduce_add_sync(0xffffffffu, Dj11 + Dj12);
        if ((t & 31) == 0) s_wpart[p][t >> 5] = make_int4(wDi, wDj0, wDj1, 0);

        __syncthreads();

        int4 v = s_wpart[p][t & 31];                 // slots 8..31 stay zero
        int Ti  = __reduce_add_sync(0xffffffffu, v.x);
        int Tj0 = __reduce_add_sync(0xffffffffu, v.y);
        int Tj1 = __reduce_add_sync(0xffffffffu, v.z);

        bool ai = Ti > 0;
        bool aj = (ai ? Tj1 : Tj0) > 0;

        if (ai) {
            #pragma unroll
            for (int q = 0; q < 4; q++) {
                g2[4*q+0] = __vadd2(g2[4*q+0], (int)bI[p][q].x);
                g2[4*q+1] = __vadd2(g2[4*q+1], (int)bI[p][q].y);
                g2[4*q+2] = __vadd2(g2[4*q+2], (int)bI[p][q].z);
                g2[4*q+3] = __vadd2(g2[4*q+3], (int)bI[p][q].w);
            }
            if (t == 0) { int ip = s_perm[2 * s]; out[ip] = -s_state[ip]; }
        }
        if (aj) {
            #pragma unroll
            for (int q = 0; q < 4; q++) {
                g2[4*q+0] = __vadd2(g2[4*q+0], (int)bJ[p][q].x);
                g2[4*q+1] = __vadd2(g2[4*q+1], (int)bJ[p][q].y);
                g2[4*q+2] = __vadd2(g2[4*q+2], (int)bJ[p][q].z);
                g2[4*q+3] = __vadd2(g2[4*q+3], (int)bJ[p][q].w);
            }
            if (t == 0) { int ip = s_perm[2 * s + 1]; out[ip] = -s_state[ip]; }
        }
        if (ai | aj) {
            #pragma unroll
            for (int k = 0; k < 16; k++) m2[k] = (int)__vmaxs2((unsigned)g2[k], 0u);
        }
    }
}

// ---------------------------------------------------------------------------
extern "C" void kernel_launch(void* const* d_in, const int* in_sizes, int n_in,
                              void* d_out, int out_size) {
    const float* W     = (const float*)d_in[0];
    const float* state = (const float*)d_in[1];
    const int*   perm  = (const int*)d_in[2];
    float*       out   = (float*)d_out;

    dim3 b1(32, 8), g1(N_BITS / 32, N_PAT / 128);
    k_buildU<<<g1, b1>>>(W, state);
    k_h0t<<<N_BITS / 256, 256>>>(state, out);
    k_main<<<1, NTHR>>>(state, perm, out);
}